// round 1
// baseline (speedup 1.0000x reference)
#include <cuda_runtime.h>
#include <math.h>
#include <stdint.h>

// Problem constants
#define B_    8192
#define SDIM  1024
#define HDIM  2048
#define DECD  1024
#define G3    3072   // 3*DEC
#define EMBD  256
#define VOCAB 169
#define VPAD  256    // padded vocab for GEMM tiling
#define TLEN  20
#define SOS_T 166
#define IGN_T 168
#define APRED 166    // pred columns kept (VOCAB-3)

// ---------------- scratch (static device globals; no allocation) -------------
__device__ float g_act[(size_t)B_ * HDIM];     // relu(s@W1+b1)      64 MB
__device__ float g_h[(size_t)B_ * DECD];       // hidden state       32 MB
__device__ float g_G0[(size_t)B_ * G3];        // h0@Wih_lo + bih    96 MB
__device__ float g_E[(size_t)VOCAB * G3];      // emb@Wih_hi          2 MB
__device__ float g_gh[(size_t)B_ * G3];        // h@Whh + bhh        96 MB
__device__ float g_logits[(size_t)B_ * VPAD];  // padded logits       8 MB
__device__ float g_WpPad[DECD * VPAD];
__device__ float g_bpPad[VPAD];
__device__ float g_nll[B_];
__device__ int   g_cnt[B_];

// ---------------- utility kernels --------------------------------------------
__global__ void zero_out_kernel(float* p, int n) {
    int i = blockIdx.x * blockDim.x + threadIdx.x;
    if (i < n) p[i] = 0.0f;
}

__global__ void zero_acc_kernel() {
    int i = blockIdx.x * blockDim.x + threadIdx.x;
    if (i < B_) { g_nll[i] = 0.0f; g_cnt[i] = 0; }
}

__global__ void pad_wp_kernel(const float* __restrict__ Wp,
                              const float* __restrict__ bp) {
    int idx = blockIdx.x * blockDim.x + threadIdx.x;
    if (idx < DECD * VPAD) {
        int k = idx >> 8, j = idx & 255;
        g_WpPad[idx] = (j < VOCAB) ? Wp[k * VOCAB + j] : 0.0f;
    }
    if (idx < VPAD) g_bpPad[idx] = (idx < VOCAB) ? bp[idx] : 0.0f;
}

// ---------------- fp32 SGEMM: C = op(A@W + bias), 128x128x8 tiles ------------
// A: [M,K] row-major, W: [K,N] row-major, C: [M,N]. N%128==0, K%8==0, M ragged ok.
template<int RELU>
__global__ __launch_bounds__(256, 2)
void sgemm128(const float* __restrict__ A, const float* __restrict__ W,
              const float* __restrict__ bias, float* __restrict__ C,
              int M, int N, int K) {
    __shared__ float As[8][128];
    __shared__ float Bs[8][128];

    const int tid = threadIdx.x;
    const int bm = blockIdx.y * 128;
    const int bn = blockIdx.x * 128;

    const int arow = tid >> 1;           // 0..127
    const int acol = (tid & 1) << 2;     // 0 or 4
    const int brow = tid >> 5;           // 0..7
    const int bcol = (tid & 31) << 2;    // 0..124

    const int tm = (tid >> 4) << 3;      // 0..120 step 8
    const int tn = (tid & 15) << 3;      // 0..120 step 8

    float acc[8][8];
#pragma unroll
    for (int i = 0; i < 8; i++)
#pragma unroll
        for (int j = 0; j < 8; j++) acc[i][j] = 0.0f;

    const bool avalid = (bm + arow) < M;
    const float* Aptr = A + (size_t)(bm + arow) * K + acol;
    const float* Bptr = W + (size_t)brow * N + bn + bcol;

    for (int k0 = 0; k0 < K; k0 += 8) {
        float4 av = avalid ? *(const float4*)(Aptr + k0)
                           : make_float4(0.f, 0.f, 0.f, 0.f);
        float4 bv = *(const float4*)(Bptr + (size_t)k0 * N);

        As[acol + 0][arow] = av.x;
        As[acol + 1][arow] = av.y;
        As[acol + 2][arow] = av.z;
        As[acol + 3][arow] = av.w;
        *(float4*)&Bs[brow][bcol] = bv;
        __syncthreads();

#pragma unroll
        for (int kk = 0; kk < 8; kk++) {
            float af[8], bf[8];
            *(float4*)(af)     = *(const float4*)&As[kk][tm];
            *(float4*)(af + 4) = *(const float4*)&As[kk][tm + 4];
            *(float4*)(bf)     = *(const float4*)&Bs[kk][tn];
            *(float4*)(bf + 4) = *(const float4*)&Bs[kk][tn + 4];
#pragma unroll
            for (int i = 0; i < 8; i++)
#pragma unroll
                for (int j = 0; j < 8; j++)
                    acc[i][j] = fmaf(af[i], bf[j], acc[i][j]);
        }
        __syncthreads();
    }

    // epilogue
#pragma unroll
    for (int i = 0; i < 8; i++) {
        int gm = bm + tm + i;
        if (gm >= M) continue;
        float* crow = C + (size_t)gm * N + bn + tn;
#pragma unroll
        for (int j = 0; j < 8; j += 4) {
            float4 v;
            float bx = bias ? bias[bn + tn + j + 0] : 0.f;
            float by = bias ? bias[bn + tn + j + 1] : 0.f;
            float bz = bias ? bias[bn + tn + j + 2] : 0.f;
            float bw = bias ? bias[bn + tn + j + 3] : 0.f;
            v.x = acc[i][j + 0] + bx;
            v.y = acc[i][j + 1] + by;
            v.z = acc[i][j + 2] + bz;
            v.w = acc[i][j + 3] + bw;
            if (RELU) {
                v.x = fmaxf(v.x, 0.f); v.y = fmaxf(v.y, 0.f);
                v.z = fmaxf(v.z, 0.f); v.w = fmaxf(v.w, 0.f);
            }
            *(float4*)(crow + j) = v;
        }
    }
}

// ---------------- GRU gate elementwise (in-place h update) -------------------
// gi = E[tok] + G0 (bih folded into G0); gh already has bhh (GEMM bias).
__global__ void gru_gate_kernel(const int* __restrict__ tgt, int t) {
    int idx = blockIdx.x * blockDim.x + threadIdx.x;   // b*DEC + j
    int b = idx >> 10;
    int j = idx & 1023;
    if (b >= B_) return;
    int tok = (t == 0) ? SOS_T : tgt[b * TLEN + (t - 1)];
    size_t base = (size_t)b * G3;
    const float* Erow = g_E + (size_t)tok * G3;

    float ir  = Erow[j]            + g_G0[base + j]            + g_gh[base + j];
    float iz  = Erow[j + DECD]     + g_G0[base + j + DECD]     + g_gh[base + j + DECD];
    float inn = Erow[j + 2 * DECD] + g_G0[base + j + 2 * DECD];
    float hn  = g_gh[base + j + 2 * DECD];

    float r = 1.0f / (1.0f + expf(-ir));
    float z = 1.0f / (1.0f + expf(-iz));
    float n = tanhf(inn + r * hn);
    float hv = g_h[idx];
    g_h[idx] = (1.0f - z) * n + z * hv;
}

// ---------------- per-row loss + argmax + scatter (1 warp / row) -------------
__global__ void loss_argmax_kernel(const int* __restrict__ tgt, int t,
                                   float* __restrict__ pred) {
    int gw = (blockIdx.x * blockDim.x + threadIdx.x) >> 5;  // row b
    int lane = threadIdx.x & 31;
    if (gw >= B_) return;
    const float* lg = g_logits + (size_t)gw * VPAD;

    float v[6];
    float vmax = -INFINITY;
    int amax = VOCAB;
#pragma unroll
    for (int i = 0; i < 6; i++) {
        int j = lane + 32 * i;
        v[i] = (j < VOCAB) ? lg[j] : -INFINITY;
        if (v[i] > vmax) { vmax = v[i]; amax = j; }
    }
#pragma unroll
    for (int off = 16; off; off >>= 1) {
        float ov = __shfl_down_sync(0xffffffffu, vmax, off);
        int oi   = __shfl_down_sync(0xffffffffu, amax, off);
        if (ov > vmax || (ov == vmax && oi < amax)) { vmax = ov; amax = oi; }
    }
    vmax = __shfl_sync(0xffffffffu, vmax, 0);
    amax = __shfl_sync(0xffffffffu, amax, 0);

    float se = 0.0f;
#pragma unroll
    for (int i = 0; i < 6; i++) {
        int j = lane + 32 * i;
        if (j < VOCAB) se += expf(v[i] - vmax);
    }
#pragma unroll
    for (int off = 16; off; off >>= 1)
        se += __shfl_down_sync(0xffffffffu, se, off);

    if (lane == 0) {
        int tg = tgt[gw * TLEN + t];
        if (tg != IGN_T) {
            float x = lg[tg];
            g_nll[gw] += -(x - vmax - logf(se));
            g_cnt[gw] += 1;
        }
        if (amax < APRED) pred[(size_t)gw * APRED + amax] = 1.0f;
    }
}

// ---------------- final reduce (deterministic, single block) -----------------
__global__ void finalize_kernel(float* out) {
    __shared__ float sf[1024];
    __shared__ int   si[1024];
    int tid = threadIdx.x;
    float s = 0.f; int c = 0;
    for (int i = tid; i < B_; i += 1024) { s += g_nll[i]; c += g_cnt[i]; }
    sf[tid] = s; si[tid] = c;
    __syncthreads();
    for (int off = 512; off > 0; off >>= 1) {
        if (tid < off) { sf[tid] += sf[tid + off]; si[tid] += si[tid + off]; }
        __syncthreads();
    }
    if (tid == 0) out[0] = sf[0] / fmaxf((float)si[0], 1.0f);
}

// ---------------- launch ------------------------------------------------------
extern "C" void kernel_launch(void* const* d_in, const int* in_sizes, int n_in,
                              void* d_out, int out_size) {
    const float* s   = (const float*)d_in[0];
    const int*   tgt = (const int*)  d_in[1];
    const float* W1  = (const float*)d_in[2];
    const float* b1  = (const float*)d_in[3];
    const float* W2  = (const float*)d_in[4];
    const float* b2  = (const float*)d_in[5];
    const float* emb = (const float*)d_in[6];
    const float* Wih = (const float*)d_in[7];
    const float* Whh = (const float*)d_in[8];
    const float* bih = (const float*)d_in[9];
    const float* bhh = (const float*)d_in[10];
    const float* Wp  = (const float*)d_in[11];
    const float* bp  = (const float*)d_in[12];
    float* out = (float*)d_out;

    float *p_act, *p_h, *p_G0, *p_E, *p_gh, *p_logits, *p_WpPad, *p_bpPad;
    cudaGetSymbolAddress((void**)&p_act,    g_act);
    cudaGetSymbolAddress((void**)&p_h,      g_h);
    cudaGetSymbolAddress((void**)&p_G0,     g_G0);
    cudaGetSymbolAddress((void**)&p_E,      g_E);
    cudaGetSymbolAddress((void**)&p_gh,     g_gh);
    cudaGetSymbolAddress((void**)&p_logits, g_logits);
    cudaGetSymbolAddress((void**)&p_WpPad,  g_WpPad);
    cudaGetSymbolAddress((void**)&p_bpPad,  g_bpPad);

    // init: zero output (poisoned), zero loss accumulators, pad Wp/bp
    zero_out_kernel<<<(out_size + 1023) / 1024, 1024>>>(out, out_size);
    zero_acc_kernel<<<(B_ + 1023) / 1024, 1024>>>();
    pad_wp_kernel<<<(DECD * VPAD + 255) / 256, 256>>>(Wp, bp);

    dim3 blk(256);
    // act = relu(s @ W1 + b1)                        [8192,2048]
    sgemm128<1><<<dim3(HDIM / 128, B_ / 128), blk>>>(s, W1, b1, p_act, B_, HDIM, SDIM);
    // h0 = act @ W2 + b2  -> g_h (initial hidden)    [8192,1024]
    sgemm128<0><<<dim3(DECD / 128, B_ / 128), blk>>>(p_act, W2, b2, p_h, B_, DECD, HDIM);
    // G0 = h0 @ Wih[EMB:,:] + bih                    [8192,3072]
    sgemm128<0><<<dim3(G3 / 128, B_ / 128), blk>>>(p_h, Wih + (size_t)EMBD * G3, bih, p_G0, B_, G3, DECD);
    // E = emb @ Wih[:EMB,:]                          [169,3072]
    sgemm128<0><<<dim3(G3 / 128, 2), blk>>>(emb, Wih, (const float*)nullptr, p_E, VOCAB, G3, EMBD);

    for (int t = 0; t < TLEN; t++) {
        // gh = h @ Whh + bhh                         [8192,3072]
        sgemm128<0><<<dim3(G3 / 128, B_ / 128), blk>>>(p_h, Whh, bhh, p_gh, B_, G3, DECD);
        // h <- GRU gate (in place)
        gru_gate_kernel<<<(B_ * DECD) / 256, 256>>>(tgt, t);
        // logits = h @ WpPad + bpPad                 [8192,256]
        sgemm128<0><<<dim3(VPAD / 128, B_ / 128), blk>>>(p_h, p_WpPad, p_bpPad, p_logits, B_, VPAD, DECD);
        // loss + argmax scatter
        loss_argmax_kernel<<<B_ / 8, 256>>>(tgt, t, out + 1);
    }

    finalize_kernel<<<1, 1024>>>(out);
}

// round 2
// speedup vs baseline: 1.0608x; 1.0608x over previous
#include <cuda_runtime.h>
#include <math.h>
#include <stdint.h>

// Problem constants
#define B_    8192
#define SDIM  1024
#define HDIM  2048
#define DECD  1024
#define G3    3072   // 3*DEC
#define EMBD  256
#define VOCAB 169
#define VPAD  256    // padded vocab for GEMM tiling
#define TLEN  20
#define SOS_T 166
#define IGN_T 168
#define APRED 166    // pred columns kept (VOCAB-3)

typedef unsigned long long u64;

// ---------------- scratch (static device globals; no allocation) -------------
__device__ float g_act[(size_t)B_ * HDIM];     // relu(s@W1+b1)
__device__ float g_h[(size_t)B_ * DECD];       // hidden state
__device__ float g_G0[(size_t)B_ * G3];        // h0@Wih_lo + bih
__device__ float g_E[(size_t)VOCAB * G3];      // emb@Wih_hi
__device__ float g_gh[(size_t)B_ * G3];        // h@Whh + bhh
__device__ float g_logits[(size_t)B_ * VPAD];  // padded logits
__device__ float g_WpPad[DECD * VPAD];
__device__ float g_bpPad[VPAD];
__device__ float g_nll[B_];
__device__ int   g_cnt[B_];

// ---------------- packed f32x2 helpers (Blackwell FFMA2 path) ----------------
__device__ __forceinline__ u64 ffma2(u64 a, u64 b, u64 c) {
    u64 d;
    asm("fma.rn.f32x2 %0, %1, %2, %3;" : "=l"(d) : "l"(a), "l"(b), "l"(c));
    return d;
}
__device__ __forceinline__ u64 pack2(float x) {
    u64 d;
    asm("mov.b64 %0, {%1, %1};" : "=l"(d) : "f"(x));
    return d;
}

// ---------------- utility kernels --------------------------------------------
__global__ void zero_out_kernel(float* p, int n) {
    int i = blockIdx.x * blockDim.x + threadIdx.x;
    if (i < n) p[i] = 0.0f;
}

__global__ void zero_acc_kernel() {
    int i = blockIdx.x * blockDim.x + threadIdx.x;
    if (i < B_) { g_nll[i] = 0.0f; g_cnt[i] = 0; }
}

__global__ void pad_wp_kernel(const float* __restrict__ Wp,
                              const float* __restrict__ bp) {
    int idx = blockIdx.x * blockDim.x + threadIdx.x;
    if (idx < DECD * VPAD) {
        int k = idx >> 8, j = idx & 255;
        g_WpPad[idx] = (j < VOCAB) ? Wp[k * VOCAB + j] : 0.0f;
    }
    if (idx < VPAD) g_bpPad[idx] = (idx < VOCAB) ? bp[idx] : 0.0f;
}

// ---------------- fp32 SGEMM with packed f32x2 FMA, double-buffered ----------
// C = op(A@W + bias). A:[M,K] row-major, W:[K,N] row-major. N%128==0, K%8==0.
template<int RELU>
__global__ __launch_bounds__(256, 2)
void sgemm128(const float* __restrict__ A, const float* __restrict__ W,
              const float* __restrict__ bias, float* __restrict__ C,
              int M, int N, int K) {
    __shared__ float As[2][8][128];
    __shared__ float Bs[2][8][128];

    const int tid = threadIdx.x;
    const int bm = blockIdx.y * 128;
    const int bn = blockIdx.x * 128;

    const int arow = tid >> 1;           // 0..127
    const int acol = (tid & 1) << 2;     // 0 or 4
    const int brow = tid >> 5;           // 0..7
    const int bcol = (tid & 31) << 2;    // 0..124

    const int tm = (tid >> 4) << 3;      // 0..120 step 8
    const int tn = (tid & 15) << 3;      // 0..120 step 8

    u64 acc[8][4];
#pragma unroll
    for (int i = 0; i < 8; i++)
#pragma unroll
        for (int j = 0; j < 4; j++) acc[i][j] = 0ull;   // = {0.f, 0.f}

    const bool avalid = (bm + arow) < M;
    const float* Aptr = A + (size_t)(bm + arow) * K + acol;
    const float* Bptr = W + (size_t)brow * N + bn + bcol;

    // preload tile 0 into buffer 0
    {
        float4 av = avalid ? *(const float4*)(Aptr)
                           : make_float4(0.f, 0.f, 0.f, 0.f);
        float4 bv = *(const float4*)(Bptr);
        As[0][acol + 0][arow] = av.x;
        As[0][acol + 1][arow] = av.y;
        As[0][acol + 2][arow] = av.z;
        As[0][acol + 3][arow] = av.w;
        *(float4*)&Bs[0][brow][bcol] = bv;
    }
    __syncthreads();

    int buf = 0;
    for (int k0 = 0; k0 < K; k0 += 8) {
        // prefetch next k-slab to registers
        const bool more = (k0 + 8) < K;
        float4 av2, bv2;
        if (more) {
            av2 = avalid ? *(const float4*)(Aptr + k0 + 8)
                         : make_float4(0.f, 0.f, 0.f, 0.f);
            bv2 = *(const float4*)(Bptr + (size_t)(k0 + 8) * N);
        }

        // compute on current buffer
#pragma unroll
        for (int kk = 0; kk < 8; kk++) {
            float af[8];
            *(float4*)(af)     = *(const float4*)&As[buf][kk][tm];
            *(float4*)(af + 4) = *(const float4*)&As[buf][kk][tm + 4];
            u64 b2[4];
            const u64* bsrc = (const u64*)&Bs[buf][kk][tn];
            b2[0] = bsrc[0]; b2[1] = bsrc[1]; b2[2] = bsrc[2]; b2[3] = bsrc[3];
#pragma unroll
            for (int i = 0; i < 8; i++) {
                u64 a2 = pack2(af[i]);
#pragma unroll
                for (int jp = 0; jp < 4; jp++)
                    acc[i][jp] = ffma2(a2, b2[jp], acc[i][jp]);
            }
        }

        // store prefetched slab into the other buffer (no one reads it yet)
        if (more) {
            buf ^= 1;
            As[buf][acol + 0][arow] = av2.x;
            As[buf][acol + 1][arow] = av2.y;
            As[buf][acol + 2][arow] = av2.z;
            As[buf][acol + 3][arow] = av2.w;
            *(float4*)&Bs[buf][brow][bcol] = bv2;
        }
        __syncthreads();
    }

    // epilogue
#pragma unroll
    for (int i = 0; i < 8; i++) {
        int gm = bm + tm + i;
        if (gm >= M) continue;
        float* crow = C + (size_t)gm * N + bn + tn;
#pragma unroll
        for (int jp = 0; jp < 4; jp += 2) {
            union { u64 u; float2 f; } c0, c1;
            c0.u = acc[i][jp];
            c1.u = acc[i][jp + 1];
            int j = jp * 2;
            float4 v;
            v.x = c0.f.x + (bias ? bias[bn + tn + j + 0] : 0.f);
            v.y = c0.f.y + (bias ? bias[bn + tn + j + 1] : 0.f);
            v.z = c1.f.x + (bias ? bias[bn + tn + j + 2] : 0.f);
            v.w = c1.f.y + (bias ? bias[bn + tn + j + 3] : 0.f);
            if (RELU) {
                v.x = fmaxf(v.x, 0.f); v.y = fmaxf(v.y, 0.f);
                v.z = fmaxf(v.z, 0.f); v.w = fmaxf(v.w, 0.f);
            }
            *(float4*)(crow + j) = v;
        }
    }
}

// ---------------- GRU gate elementwise (in-place h update) -------------------
__global__ void gru_gate_kernel(const int* __restrict__ tgt, int t) {
    int idx = blockIdx.x * blockDim.x + threadIdx.x;   // b*DEC + j
    int b = idx >> 10;
    int j = idx & 1023;
    if (b >= B_) return;
    int tok = (t == 0) ? SOS_T : tgt[b * TLEN + (t - 1)];
    size_t base = (size_t)b * G3;
    const float* Erow = g_E + (size_t)tok * G3;

    float ir  = Erow[j]            + g_G0[base + j]            + g_gh[base + j];
    float iz  = Erow[j + DECD]     + g_G0[base + j + DECD]     + g_gh[base + j + DECD];
    float inn = Erow[j + 2 * DECD] + g_G0[base + j + 2 * DECD];
    float hn  = g_gh[base + j + 2 * DECD];

    float r = 1.0f / (1.0f + expf(-ir));
    float z = 1.0f / (1.0f + expf(-iz));
    float n = tanhf(inn + r * hn);
    float hv = g_h[idx];
    g_h[idx] = (1.0f - z) * n + z * hv;
}

// ---------------- per-row loss + argmax + scatter (1 warp / row) -------------
__global__ void loss_argmax_kernel(const int* __restrict__ tgt, int t,
                                   float* __restrict__ pred) {
    int gw = (blockIdx.x * blockDim.x + threadIdx.x) >> 5;  // row b
    int lane = threadIdx.x & 31;
    if (gw >= B_) return;
    const float* lg = g_logits + (size_t)gw * VPAD;

    float v[6];
    float vmax = -INFINITY;
    int amax = VOCAB;
#pragma unroll
    for (int i = 0; i < 6; i++) {
        int j = lane + 32 * i;
        v[i] = (j < VOCAB) ? lg[j] : -INFINITY;
        if (v[i] > vmax) { vmax = v[i]; amax = j; }
    }
#pragma unroll
    for (int off = 16; off; off >>= 1) {
        float ov = __shfl_down_sync(0xffffffffu, vmax, off);
        int oi   = __shfl_down_sync(0xffffffffu, amax, off);
        if (ov > vmax || (ov == vmax && oi < amax)) { vmax = ov; amax = oi; }
    }
    vmax = __shfl_sync(0xffffffffu, vmax, 0);
    amax = __shfl_sync(0xffffffffu, amax, 0);

    float se = 0.0f;
#pragma unroll
    for (int i = 0; i < 6; i++) {
        int j = lane + 32 * i;
        if (j < VOCAB) se += expf(v[i] - vmax);
    }
#pragma unroll
    for (int off = 16; off; off >>= 1)
        se += __shfl_down_sync(0xffffffffu, se, off);

    if (lane == 0) {
        int tg = tgt[gw * TLEN + t];
        if (tg != IGN_T) {
            float x = lg[tg];
            g_nll[gw] += -(x - vmax - logf(se));
            g_cnt[gw] += 1;
        }
        if (amax < APRED) pred[(size_t)gw * APRED + amax] = 1.0f;
    }
}

// ---------------- final reduce (deterministic, single block) -----------------
__global__ void finalize_kernel(float* out) {
    __shared__ float sf[1024];
    __shared__ int   si[1024];
    int tid = threadIdx.x;
    float s = 0.f; int c = 0;
    for (int i = tid; i < B_; i += 1024) { s += g_nll[i]; c += g_cnt[i]; }
    sf[tid] = s; si[tid] = c;
    __syncthreads();
    for (int off = 512; off > 0; off >>= 1) {
        if (tid < off) { sf[tid] += sf[tid + off]; si[tid] += si[tid + off]; }
        __syncthreads();
    }
    if (tid == 0) out[0] = sf[0] / fmaxf((float)si[0], 1.0f);
}

// ---------------- launch ------------------------------------------------------
extern "C" void kernel_launch(void* const* d_in, const int* in_sizes, int n_in,
                              void* d_out, int out_size) {
    const float* s   = (const float*)d_in[0];
    const int*   tgt = (const int*)  d_in[1];
    const float* W1  = (const float*)d_in[2];
    const float* b1  = (const float*)d_in[3];
    const float* W2  = (const float*)d_in[4];
    const float* b2  = (const float*)d_in[5];
    const float* emb = (const float*)d_in[6];
    const float* Wih = (const float*)d_in[7];
    const float* Whh = (const float*)d_in[8];
    const float* bih = (const float*)d_in[9];
    const float* bhh = (const float*)d_in[10];
    const float* Wp  = (const float*)d_in[11];
    const float* bp  = (const float*)d_in[12];
    float* out = (float*)d_out;

    float *p_act, *p_h, *p_G0, *p_E, *p_gh, *p_logits, *p_WpPad, *p_bpPad;
    cudaGetSymbolAddress((void**)&p_act,    g_act);
    cudaGetSymbolAddress((void**)&p_h,      g_h);
    cudaGetSymbolAddress((void**)&p_G0,     g_G0);
    cudaGetSymbolAddress((void**)&p_E,      g_E);
    cudaGetSymbolAddress((void**)&p_gh,     g_gh);
    cudaGetSymbolAddress((void**)&p_logits, g_logits);
    cudaGetSymbolAddress((void**)&p_WpPad,  g_WpPad);
    cudaGetSymbolAddress((void**)&p_bpPad,  g_bpPad);

    // init: zero output (poisoned), zero loss accumulators, pad Wp/bp
    zero_out_kernel<<<(out_size + 1023) / 1024, 1024>>>(out, out_size);
    zero_acc_kernel<<<(B_ + 1023) / 1024, 1024>>>();
    pad_wp_kernel<<<(DECD * VPAD + 255) / 256, 256>>>(Wp, bp);

    dim3 blk(256);
    // act = relu(s @ W1 + b1)                        [8192,2048]
    sgemm128<1><<<dim3(HDIM / 128, B_ / 128), blk>>>(s, W1, b1, p_act, B_, HDIM, SDIM);
    // h0 = act @ W2 + b2  -> g_h (initial hidden)    [8192,1024]
    sgemm128<0><<<dim3(DECD / 128, B_ / 128), blk>>>(p_act, W2, b2, p_h, B_, DECD, HDIM);
    // G0 = h0 @ Wih[EMB:,:] + bih                    [8192,3072]
    sgemm128<0><<<dim3(G3 / 128, B_ / 128), blk>>>(p_h, Wih + (size_t)EMBD * G3, bih, p_G0, B_, G3, DECD);
    // E = emb @ Wih[:EMB,:]                          [169,3072]
    sgemm128<0><<<dim3(G3 / 128, 2), blk>>>(emb, Wih, (const float*)nullptr, p_E, VOCAB, G3, EMBD);

    for (int t = 0; t < TLEN; t++) {
        // gh = h @ Whh + bhh                         [8192,3072]
        sgemm128<0><<<dim3(G3 / 128, B_ / 128), blk>>>(p_h, Whh, bhh, p_gh, B_, G3, DECD);
        // h <- GRU gate (in place)
        gru_gate_kernel<<<(B_ * DECD) / 256, 256>>>(tgt, t);
        // logits = h @ WpPad + bpPad                 [8192,256]
        sgemm128<0><<<dim3(VPAD / 128, B_ / 128), blk>>>(p_h, p_WpPad, p_bpPad, p_logits, B_, VPAD, DECD);
        // loss + argmax scatter
        loss_argmax_kernel<<<B_ / 8, 256>>>(tgt, t, out + 1);
    }

    finalize_kernel<<<1, 1024>>>(out);
}

// round 4
// speedup vs baseline: 1.4105x; 1.3297x over previous
#include <cuda_runtime.h>
#include <math.h>
#include <stdint.h>

// Problem constants
#define B_    8192
#define SDIM  1024
#define HDIM  2048
#define DECD  1024
#define G3    3072   // 3*DEC
#define EMBD  256
#define VOCAB 169
#define VPAD  256
#define TLEN  20
#define SOS_T 166
#define IGN_T 168
#define APRED 166

typedef unsigned long long u64;
typedef unsigned int u32;

// ---------------- scratch (static device globals) ----------------------------
__device__ float g_act[(size_t)B_ * HDIM];
__device__ float g_h[(size_t)B_ * DECD];
__device__ float g_h_hi[(size_t)B_ * DECD];
__device__ float g_h_lo[(size_t)B_ * DECD];
__device__ float g_G0[(size_t)B_ * G3];
__device__ float g_E[(size_t)VOCAB * G3];
__device__ float g_gh[(size_t)B_ * G3];
__device__ float g_Whi[(size_t)DECD * G3];    // Whh split hi (k-major [1024][3072])
__device__ float g_Wlo[(size_t)DECD * G3];
__device__ float g_Wihi[(size_t)DECD * G3];   // Wih[EMB:,:] split (k-major)
__device__ float g_Wilo[(size_t)DECD * G3];
__device__ float g_WpPad[DECD * VPAD];
__device__ float g_Wphi[DECD * VPAD];
__device__ float g_Wplo[DECD * VPAD];
__device__ float g_bpPad[VPAD];
__device__ float g_logits[(size_t)B_ * VPAD];
__device__ float g_nll[B_];
__device__ int   g_cnt[B_];

// ---------------- helpers -----------------------------------------------------
__device__ __forceinline__ u64 ffma2(u64 a, u64 b, u64 c) {
    u64 d;
    asm("fma.rn.f32x2 %0, %1, %2, %3;" : "=l"(d) : "l"(a), "l"(b), "l"(c));
    return d;
}
__device__ __forceinline__ u64 pack2(float x) {
    u64 d;
    asm("mov.b64 %0, {%1, %1};" : "=l"(d) : "f"(x));
    return d;
}
__device__ __forceinline__ float tf32_rna(float x) {
    u32 r;
    asm("cvt.rna.tf32.f32 %0, %1;" : "=r"(r) : "f"(x));
    return __uint_as_float(r);
}
// m16n8k8 tf32 MMA, accumulate in place
__device__ __forceinline__ void mma_tf32(float* d, const u32* a, u32 b0, u32 b1) {
    asm volatile(
        "mma.sync.aligned.m16n8k8.row.col.f32.tf32.tf32.f32 "
        "{%0,%1,%2,%3}, {%4,%5,%6,%7}, {%8,%9}, {%0,%1,%2,%3};"
        : "+f"(d[0]), "+f"(d[1]), "+f"(d[2]), "+f"(d[3])
        : "r"(a[0]), "r"(a[1]), "r"(a[2]), "r"(a[3]), "r"(b0), "r"(b1));
}

// ---------------- utility kernels ---------------------------------------------
__global__ void zero_out_kernel(float* p, int n) {
    int i = blockIdx.x * blockDim.x + threadIdx.x;
    if (i < n) p[i] = 0.0f;
}
__global__ void zero_acc_kernel() {
    int i = blockIdx.x * blockDim.x + threadIdx.x;
    if (i < B_) { g_nll[i] = 0.0f; g_cnt[i] = 0; }
}
__global__ void pad_wp_kernel(const float* __restrict__ Wp, const float* __restrict__ bp) {
    int idx = blockIdx.x * blockDim.x + threadIdx.x;
    if (idx < DECD * VPAD) {
        int k = idx >> 8, j = idx & 255;
        g_WpPad[idx] = (j < VOCAB) ? Wp[k * VOCAB + j] : 0.0f;
    }
    if (idx < VPAD) g_bpPad[idx] = (idx < VOCAB) ? bp[idx] : 0.0f;
}
__global__ void split_kernel(const float* __restrict__ src, float* __restrict__ hi,
                             float* __restrict__ lo, int n) {
    int i = blockIdx.x * blockDim.x + threadIdx.x;
    if (i >= n) return;
    float x = src[i];
    float h = tf32_rna(x);
    hi[i] = h;
    lo[i] = tf32_rna(x - h);
}

// ---------------- packed fp32 SGEMM (setup GEMMs) -----------------------------
template<int RELU>
__global__ __launch_bounds__(256, 2)
void sgemm128(const float* __restrict__ A, const float* __restrict__ W,
              const float* __restrict__ bias, float* __restrict__ C,
              int M, int N, int K) {
    __shared__ float As[2][8][128];
    __shared__ float Bs[2][8][128];
    const int tid = threadIdx.x;
    const int bm = blockIdx.y * 128, bn = blockIdx.x * 128;
    const int arow = tid >> 1, acol = (tid & 1) << 2;
    const int brow = tid >> 5, bcol = (tid & 31) << 2;
    const int tm = (tid >> 4) << 3, tn = (tid & 15) << 3;

    u64 acc[8][4];
#pragma unroll
    for (int i = 0; i < 8; i++)
#pragma unroll
        for (int j = 0; j < 4; j++) acc[i][j] = 0ull;

    const bool avalid = (bm + arow) < M;
    const float* Aptr = A + (size_t)(bm + arow) * K + acol;
    const float* Bptr = W + (size_t)brow * N + bn + bcol;
    {
        float4 av = avalid ? *(const float4*)(Aptr) : make_float4(0.f,0.f,0.f,0.f);
        float4 bv = *(const float4*)(Bptr);
        As[0][acol+0][arow]=av.x; As[0][acol+1][arow]=av.y;
        As[0][acol+2][arow]=av.z; As[0][acol+3][arow]=av.w;
        *(float4*)&Bs[0][brow][bcol] = bv;
    }
    __syncthreads();
    int buf = 0;
    for (int k0 = 0; k0 < K; k0 += 8) {
        const bool more = (k0 + 8) < K;
        float4 av2, bv2;
        if (more) {
            av2 = avalid ? *(const float4*)(Aptr + k0 + 8) : make_float4(0.f,0.f,0.f,0.f);
            bv2 = *(const float4*)(Bptr + (size_t)(k0 + 8) * N);
        }
#pragma unroll
        for (int kk = 0; kk < 8; kk++) {
            float af[8];
            *(float4*)(af)   = *(const float4*)&As[buf][kk][tm];
            *(float4*)(af+4) = *(const float4*)&As[buf][kk][tm+4];
            u64 b2[4];
            const u64* bsrc = (const u64*)&Bs[buf][kk][tn];
            b2[0]=bsrc[0]; b2[1]=bsrc[1]; b2[2]=bsrc[2]; b2[3]=bsrc[3];
#pragma unroll
            for (int i = 0; i < 8; i++) {
                u64 a2 = pack2(af[i]);
#pragma unroll
                for (int jp = 0; jp < 4; jp++) acc[i][jp] = ffma2(a2, b2[jp], acc[i][jp]);
            }
        }
        if (more) {
            buf ^= 1;
            As[buf][acol+0][arow]=av2.x; As[buf][acol+1][arow]=av2.y;
            As[buf][acol+2][arow]=av2.z; As[buf][acol+3][arow]=av2.w;
            *(float4*)&Bs[buf][brow][bcol] = bv2;
        }
        __syncthreads();
    }
#pragma unroll
    for (int i = 0; i < 8; i++) {
        int gm = bm + tm + i;
        if (gm >= M) continue;
        float* crow = C + (size_t)gm * N + bn + tn;
#pragma unroll
        for (int jp = 0; jp < 4; jp += 2) {
            union { u64 u; float2 f; } c0, c1;
            c0.u = acc[i][jp]; c1.u = acc[i][jp+1];
            int j = jp * 2;
            float4 v;
            v.x = c0.f.x + (bias ? bias[bn+tn+j+0] : 0.f);
            v.y = c0.f.y + (bias ? bias[bn+tn+j+1] : 0.f);
            v.z = c1.f.x + (bias ? bias[bn+tn+j+2] : 0.f);
            v.w = c1.f.y + (bias ? bias[bn+tn+j+3] : 0.f);
            if (RELU) { v.x=fmaxf(v.x,0.f); v.y=fmaxf(v.y,0.f); v.z=fmaxf(v.z,0.f); v.w=fmaxf(v.w,0.f); }
            *(float4*)(crow + j) = v;
        }
    }
}

// ---------------- TF32 3-pass MMA GEMM: C = A @ B + bias ----------------------
// A (hi/lo): [8192,1024] row-major. B (hi/lo): [1024,N] k-major. K fixed 1024.
// Grid (N/128, 64). CTA tile 128x128, 8 warps of 32x64.
// SMEM floats: Ash[128*36] Asl[128*36] Bsh[32*136] Bsl[32*136] sbias[128]
#define MMA_SM_FLOATS (4608*2 + 4352*2 + 128)
#define MMA_SM_BYTES  (MMA_SM_FLOATS * 4)

__global__ __launch_bounds__(256, 2)
void mma3_gemm(const float* __restrict__ Ahi, const float* __restrict__ Alo,
               const float* __restrict__ Bhi, const float* __restrict__ Blo,
               const float* __restrict__ bias, float* __restrict__ C,
               int ldB, int ldC) {
    extern __shared__ float sm[];
    float* Ash = sm;
    float* Asl = sm + 4608;
    float* Bsh = sm + 9216;
    float* Bsl = sm + 13568;
    float* sbias = sm + 17920;

    const int tid = threadIdx.x;
    const int w = tid >> 5, lane = tid & 31;
    const int gr = lane >> 2, tq = lane & 3;
    const int warp_m = (w & 3) * 32, warp_n = (w >> 2) * 64;
    const size_t m_base = (size_t)blockIdx.y * 128;
    const int n_base = blockIdx.x * 128;

    if (tid < 128) sbias[tid] = bias[n_base + tid];

    const float* Ah = Ahi + m_base * DECD;
    const float* Al = Alo + m_base * DECD;

    float d[2][8][4];
#pragma unroll
    for (int i = 0; i < 2; i++)
#pragma unroll
        for (int j = 0; j < 8; j++)
#pragma unroll
            for (int q = 0; q < 4; q++) d[i][j][q] = 0.0f;

    for (int k0 = 0; k0 < 1024; k0 += 32) {
        __syncthreads();
#pragma unroll
        for (int it = 0; it < 4; it++) {
            int fi = tid + it * 256;
            int m = fi >> 3, kg = fi & 7;
            *(float4*)&Ash[m * 36 + kg * 4] = *(const float4*)&Ah[(size_t)m * DECD + k0 + kg * 4];
            *(float4*)&Asl[m * 36 + kg * 4] = *(const float4*)&Al[(size_t)m * DECD + k0 + kg * 4];
            int kr = fi >> 5, n4 = fi & 31;
            *(float4*)&Bsh[kr * 136 + n4 * 4] = *(const float4*)&Bhi[(size_t)(k0 + kr) * ldB + n_base + n4 * 4];
            *(float4*)&Bsl[kr * 136 + n4 * 4] = *(const float4*)&Blo[(size_t)(k0 + kr) * ldB + n_base + n4 * 4];
        }
        __syncthreads();

#pragma unroll
        for (int kk = 0; kk < 32; kk += 8) {
            u32 ah[2][4], al[2][4];
#pragma unroll
            for (int i = 0; i < 2; i++) {
                int r = (warp_m + i * 16 + gr) * 36 + kk + tq;
                ah[i][0] = __float_as_uint(Ash[r]);
                ah[i][1] = __float_as_uint(Ash[r + 288]);
                ah[i][2] = __float_as_uint(Ash[r + 4]);
                ah[i][3] = __float_as_uint(Ash[r + 292]);
                al[i][0] = __float_as_uint(Asl[r]);
                al[i][1] = __float_as_uint(Asl[r + 288]);
                al[i][2] = __float_as_uint(Asl[r + 4]);
                al[i][3] = __float_as_uint(Asl[r + 292]);
            }
#pragma unroll
            for (int j = 0; j < 8; j++) {
                int bb = (kk + tq) * 136 + warp_n + j * 8 + gr;
                u32 bh0 = __float_as_uint(Bsh[bb]);
                u32 bh1 = __float_as_uint(Bsh[bb + 544]);
                u32 bl0 = __float_as_uint(Bsl[bb]);
                u32 bl1 = __float_as_uint(Bsl[bb + 544]);
#pragma unroll
                for (int i = 0; i < 2; i++) {
                    mma_tf32(d[i][j], ah[i], bh0, bh1);
                    mma_tf32(d[i][j], ah[i], bl0, bl1);
                    mma_tf32(d[i][j], al[i], bh0, bh1);
                }
            }
        }
    }

    // epilogue: direct global stores (32B-sector aligned float2 quads)
#pragma unroll
    for (int i = 0; i < 2; i++) {
        size_t r0 = m_base + warp_m + i * 16 + gr;
#pragma unroll
        for (int j = 0; j < 8; j++) {
            int cn = warp_n + j * 8 + 2 * tq;
            float bx = sbias[cn], by = sbias[cn + 1];
            float2 v0 = make_float2(d[i][j][0] + bx, d[i][j][1] + by);
            float2 v1 = make_float2(d[i][j][2] + bx, d[i][j][3] + by);
            *(float2*)&C[r0 * ldC + n_base + cn] = v0;
            *(float2*)&C[(r0 + 8) * ldC + n_base + cn] = v1;
        }
    }
}

// ---------------- GRU gate (also emits tf32 split of new h) ------------------
__global__ void gru_gate_kernel(const int* __restrict__ tgt, int t) {
    int idx = blockIdx.x * blockDim.x + threadIdx.x;
    int b = idx >> 10, j = idx & 1023;
    if (b >= B_) return;
    int tok = (t == 0) ? SOS_T : tgt[b * TLEN + (t - 1)];
    size_t base = (size_t)b * G3;
    const float* Erow = g_E + (size_t)tok * G3;

    float ir  = Erow[j]          + g_G0[base + j]          + g_gh[base + j];
    float iz  = Erow[j + DECD]   + g_G0[base + j + DECD]   + g_gh[base + j + DECD];
    float inn = Erow[j + 2*DECD] + g_G0[base + j + 2*DECD];
    float hn  = g_gh[base + j + 2*DECD];

    float r = 1.0f / (1.0f + expf(-ir));
    float z = 1.0f / (1.0f + expf(-iz));
    float n = tanhf(inn + r * hn);
    float hv = g_h[idx];
    float hnew = (1.0f - z) * n + z * hv;
    g_h[idx] = hnew;
    float hi = tf32_rna(hnew);
    g_h_hi[idx] = hi;
    g_h_lo[idx] = tf32_rna(hnew - hi);
}

// ---------------- per-row loss + argmax + scatter -----------------------------
__global__ void loss_argmax_kernel(const int* __restrict__ tgt, int t,
                                   float* __restrict__ pred) {
    int gw = (blockIdx.x * blockDim.x + threadIdx.x) >> 5;
    int lane = threadIdx.x & 31;
    if (gw >= B_) return;
    const float* lg = g_logits + (size_t)gw * VPAD;

    float v[6];
    float vmax = -INFINITY;
    int amax = VOCAB;
#pragma unroll
    for (int i = 0; i < 6; i++) {
        int j = lane + 32 * i;
        v[i] = (j < VOCAB) ? lg[j] : -INFINITY;
        if (v[i] > vmax) { vmax = v[i]; amax = j; }
    }
#pragma unroll
    for (int off = 16; off; off >>= 1) {
        float ov = __shfl_down_sync(0xffffffffu, vmax, off);
        int oi   = __shfl_down_sync(0xffffffffu, amax, off);
        if (ov > vmax || (ov == vmax && oi < amax)) { vmax = ov; amax = oi; }
    }
    vmax = __shfl_sync(0xffffffffu, vmax, 0);
    amax = __shfl_sync(0xffffffffu, amax, 0);

    float se = 0.0f;
#pragma unroll
    for (int i = 0; i < 6; i++) {
        int j = lane + 32 * i;
        if (j < VOCAB) se += expf(v[i] - vmax);
    }
#pragma unroll
    for (int off = 16; off; off >>= 1)
        se += __shfl_down_sync(0xffffffffu, se, off);

    if (lane == 0) {
        int tg = tgt[gw * TLEN + t];
        if (tg != IGN_T) {
            float x = lg[tg];
            g_nll[gw] += -(x - vmax - logf(se));
            g_cnt[gw] += 1;
        }
        if (amax < APRED) pred[(size_t)gw * APRED + amax] = 1.0f;
    }
}

__global__ void finalize_kernel(float* out) {
    __shared__ float sf[1024];
    __shared__ int   si[1024];
    int tid = threadIdx.x;
    float s = 0.f; int c = 0;
    for (int i = tid; i < B_; i += 1024) { s += g_nll[i]; c += g_cnt[i]; }
    sf[tid] = s; si[tid] = c;
    __syncthreads();
    for (int off = 512; off > 0; off >>= 1) {
        if (tid < off) { sf[tid] += sf[tid + off]; si[tid] += si[tid + off]; }
        __syncthreads();
    }
    if (tid == 0) out[0] = sf[0] / fmaxf((float)si[0], 1.0f);
}

// ---------------- launch -------------------------------------------------------
extern "C" void kernel_launch(void* const* d_in, const int* in_sizes, int n_in,
                              void* d_out, int out_size) {
    const float* s   = (const float*)d_in[0];
    const int*   tgt = (const int*)  d_in[1];
    const float* W1  = (const float*)d_in[2];
    const float* b1  = (const float*)d_in[3];
    const float* W2  = (const float*)d_in[4];
    const float* b2  = (const float*)d_in[5];
    const float* emb = (const float*)d_in[6];
    const float* Wih = (const float*)d_in[7];
    const float* Whh = (const float*)d_in[8];
    const float* bih = (const float*)d_in[9];
    const float* bhh = (const float*)d_in[10];
    const float* Wp  = (const float*)d_in[11];
    const float* bp  = (const float*)d_in[12];
    float* out = (float*)d_out;

    float *p_act, *p_h, *p_hhi, *p_hlo, *p_G0, *p_E, *p_gh;
    float *p_Whi, *p_Wlo, *p_Wihi, *p_Wilo, *p_WpPad, *p_Wphi, *p_Wplo, *p_bpPad, *p_logits;
    cudaGetSymbolAddress((void**)&p_act,    g_act);
    cudaGetSymbolAddress((void**)&p_h,      g_h);
    cudaGetSymbolAddress((void**)&p_hhi,    g_h_hi);
    cudaGetSymbolAddress((void**)&p_hlo,    g_h_lo);
    cudaGetSymbolAddress((void**)&p_G0,     g_G0);
    cudaGetSymbolAddress((void**)&p_E,      g_E);
    cudaGetSymbolAddress((void**)&p_gh,     g_gh);
    cudaGetSymbolAddress((void**)&p_Whi,    g_Whi);
    cudaGetSymbolAddress((void**)&p_Wlo,    g_Wlo);
    cudaGetSymbolAddress((void**)&p_Wihi,   g_Wihi);
    cudaGetSymbolAddress((void**)&p_Wilo,   g_Wilo);
    cudaGetSymbolAddress((void**)&p_WpPad,  g_WpPad);
    cudaGetSymbolAddress((void**)&p_Wphi,   g_Wphi);
    cudaGetSymbolAddress((void**)&p_Wplo,   g_Wplo);
    cudaGetSymbolAddress((void**)&p_bpPad,  g_bpPad);
    cudaGetSymbolAddress((void**)&p_logits, g_logits);

    cudaFuncSetAttribute(mma3_gemm, cudaFuncAttributeMaxDynamicSharedMemorySize,
                         MMA_SM_BYTES);

    // init + one-time weight prep
    zero_out_kernel<<<(out_size + 1023) / 1024, 1024>>>(out, out_size);
    zero_acc_kernel<<<(B_ + 1023) / 1024, 1024>>>();
    pad_wp_kernel<<<(DECD * VPAD + 255) / 256, 256>>>(Wp, bp);
    split_kernel<<<(DECD * G3 + 255) / 256, 256>>>(Whh, p_Whi, p_Wlo, DECD * G3);
    split_kernel<<<(DECD * G3 + 255) / 256, 256>>>(Wih + (size_t)EMBD * G3, p_Wihi, p_Wilo, DECD * G3);
    split_kernel<<<(DECD * VPAD + 255) / 256, 256>>>(p_WpPad, p_Wphi, p_Wplo, DECD * VPAD);

    dim3 blk(256);
    // act = relu(s @ W1 + b1); h0 = act @ W2 + b2
    sgemm128<1><<<dim3(HDIM / 128, B_ / 128), blk>>>(s, W1, b1, p_act, B_, HDIM, SDIM);
    sgemm128<0><<<dim3(DECD / 128, B_ / 128), blk>>>(p_act, W2, b2, p_h, B_, DECD, HDIM);
    split_kernel<<<(B_ * DECD + 255) / 256, 256>>>(p_h, p_hhi, p_hlo, B_ * DECD);
    // G0 = h0 @ Wih[EMB:,:] + bih   (TF32 3-pass MMA)
    mma3_gemm<<<dim3(G3 / 128, B_ / 128), blk, MMA_SM_BYTES>>>(
        p_hhi, p_hlo, p_Wihi, p_Wilo, bih, p_G0, G3, G3);
    // E = emb @ Wih[:EMB,:]  (small, FFMA; zero-bias via bpPad trick not needed)
    sgemm128<0><<<dim3(G3 / 128, 2), blk>>>(emb, Wih, (const float*)nullptr, p_E, VOCAB, G3, EMBD);

    for (int t = 0; t < TLEN; t++) {
        // gh = h @ Whh + bhh
        mma3_gemm<<<dim3(G3 / 128, B_ / 128), blk, MMA_SM_BYTES>>>(
            p_hhi, p_hlo, p_Whi, p_Wlo, bhh, p_gh, G3, G3);
        gru_gate_kernel<<<(B_ * DECD) / 256, 256>>>(tgt, t);
        // logits = h @ WpPad + bpPad
        mma3_gemm<<<dim3(VPAD / 128, B_ / 128), blk, MMA_SM_BYTES>>>(
            p_hhi, p_hlo, p_Wphi, p_Wplo, p_bpPad, p_logits, VPAD, VPAD);
        loss_argmax_kernel<<<B_ / 8, 256>>>(tgt, t, out + 1);
    }

    finalize_kernel<<<1, 1024>>>(out);
}

// round 6
// speedup vs baseline: 1.4564x; 1.0325x over previous
#include <cuda_runtime.h>
#include <math.h>
#include <stdint.h>

// Problem constants
#define B_    8192
#define SDIM  1024
#define HDIM  2048
#define DECD  1024
#define G3    3072
#define EMBD  256
#define VOCAB 169
#define VPAD  256
#define TLEN  20
#define SOS_T 166
#define IGN_T 168
#define APRED 166

typedef unsigned long long u64;
typedef unsigned int u32;

// ---------------- scratch (static device globals) ----------------------------
__device__ float g_act[(size_t)B_ * HDIM];
__device__ float g_h[(size_t)B_ * DECD];
__device__ float g_h_hi[(size_t)B_ * DECD];
__device__ float g_h_lo[(size_t)B_ * DECD];
__device__ float g_G0[(size_t)B_ * G3];
__device__ float g_E[(size_t)VOCAB * G3];
__device__ float g_gh[(size_t)B_ * G3];
__device__ float g_Whi[(size_t)DECD * G3];
__device__ float g_Wlo[(size_t)DECD * G3];
__device__ float g_Wihi[(size_t)DECD * G3];
__device__ float g_Wilo[(size_t)DECD * G3];
__device__ float g_WpPad[DECD * VPAD];
__device__ float g_Wphi[DECD * VPAD];
__device__ float g_Wplo[DECD * VPAD];
__device__ float g_bpPad[VPAD];
__device__ float g_logits[(size_t)B_ * VPAD];
__device__ float g_nll[B_];
__device__ int   g_cnt[B_];

// ---------------- helpers -----------------------------------------------------
__device__ __forceinline__ float tf32_rna(float x) {
    u32 r;
    asm("cvt.rna.tf32.f32 %0, %1;" : "=r"(r) : "f"(x));
    return __uint_as_float(r);
}
__device__ __forceinline__ void mma_tf32(float* d, const u32* a, u32 b0, u32 b1) {
    asm volatile(
        "mma.sync.aligned.m16n8k8.row.col.f32.tf32.tf32.f32 "
        "{%0,%1,%2,%3}, {%4,%5,%6,%7}, {%8,%9}, {%0,%1,%2,%3};"
        : "+f"(d[0]), "+f"(d[1]), "+f"(d[2]), "+f"(d[3])
        : "r"(a[0]), "r"(a[1]), "r"(a[2]), "r"(a[3]), "r"(b0), "r"(b1));
}
__device__ __forceinline__ u32 smem_u32(const void* p) {
    u32 a;
    asm("{ .reg .u64 t; cvta.to.shared.u64 t, %1; cvt.u32.u64 %0, t; }" : "=r"(a) : "l"(p));
    return a;
}
__device__ __forceinline__ void cp16(u32 dst, const void* src) {
    asm volatile("cp.async.cg.shared.global [%0], [%1], 16;" :: "r"(dst), "l"(src));
}
#define CP_COMMIT() asm volatile("cp.async.commit_group;" ::: "memory")
#define CP_WAIT1()  asm volatile("cp.async.wait_group 1;" ::: "memory")
#define CP_WAIT0()  asm volatile("cp.async.wait_group 0;" ::: "memory")

typedef unsigned long long ull;
__device__ __forceinline__ ull ffma2(ull a, ull b, ull c) {
    ull d;
    asm("fma.rn.f32x2 %0, %1, %2, %3;" : "=l"(d) : "l"(a), "l"(b), "l"(c));
    return d;
}
__device__ __forceinline__ ull pack2(float x) {
    ull d;
    asm("mov.b64 %0, {%1, %1};" : "=l"(d) : "f"(x));
    return d;
}

// ---------------- utility kernels ---------------------------------------------
__global__ void zero_out_kernel(float* p, int n) {
    int i = blockIdx.x * blockDim.x + threadIdx.x;
    if (i < n) p[i] = 0.0f;
}
__global__ void zero_acc_kernel() {
    int i = blockIdx.x * blockDim.x + threadIdx.x;
    if (i < B_) { g_nll[i] = 0.0f; g_cnt[i] = 0; }
}
__global__ void pad_wp_kernel(const float* __restrict__ Wp, const float* __restrict__ bp) {
    int idx = blockIdx.x * blockDim.x + threadIdx.x;
    if (idx < DECD * VPAD) {
        int k = idx >> 8, j = idx & 255;
        g_WpPad[idx] = (j < VOCAB) ? Wp[k * VOCAB + j] : 0.0f;
    }
    if (idx < VPAD) g_bpPad[idx] = (idx < VOCAB) ? bp[idx] : 0.0f;
}
__global__ void split_kernel(const float* __restrict__ src, float* __restrict__ hi,
                             float* __restrict__ lo, int n) {
    int i = blockIdx.x * blockDim.x + threadIdx.x;
    if (i >= n) return;
    float x = src[i];
    float h = tf32_rna(x);
    hi[i] = h;
    lo[i] = tf32_rna(x - h);
}

// ---------------- packed fp32 SGEMM (exact setup GEMMs: W1, W2, E) ------------
template<int RELU>
__global__ __launch_bounds__(256, 2)
void sgemm128(const float* __restrict__ A, const float* __restrict__ W,
              const float* __restrict__ bias, float* __restrict__ C,
              int M, int N, int K) {
    __shared__ float As[2][8][128];
    __shared__ float Bs[2][8][128];
    const int tid = threadIdx.x;
    const int bm = blockIdx.y * 128, bn = blockIdx.x * 128;
    const int arow = tid >> 1, acol = (tid & 1) << 2;
    const int brow = tid >> 5, bcol = (tid & 31) << 2;
    const int tm = (tid >> 4) << 3, tn = (tid & 15) << 3;
    ull acc[8][4];
#pragma unroll
    for (int i = 0; i < 8; i++)
#pragma unroll
        for (int j = 0; j < 4; j++) acc[i][j] = 0ull;
    const bool avalid = (bm + arow) < M;
    const float* Aptr = A + (size_t)(bm + arow) * K + acol;
    const float* Bptr = W + (size_t)brow * N + bn + bcol;
    {
        float4 av = avalid ? *(const float4*)(Aptr) : make_float4(0.f,0.f,0.f,0.f);
        float4 bv = *(const float4*)(Bptr);
        As[0][acol+0][arow]=av.x; As[0][acol+1][arow]=av.y;
        As[0][acol+2][arow]=av.z; As[0][acol+3][arow]=av.w;
        *(float4*)&Bs[0][brow][bcol] = bv;
    }
    __syncthreads();
    int buf = 0;
    for (int k0 = 0; k0 < K; k0 += 8) {
        const bool more = (k0 + 8) < K;
        float4 av2, bv2;
        if (more) {
            av2 = avalid ? *(const float4*)(Aptr + k0 + 8) : make_float4(0.f,0.f,0.f,0.f);
            bv2 = *(const float4*)(Bptr + (size_t)(k0 + 8) * N);
        }
#pragma unroll
        for (int kk = 0; kk < 8; kk++) {
            float af[8];
            *(float4*)(af)   = *(const float4*)&As[buf][kk][tm];
            *(float4*)(af+4) = *(const float4*)&As[buf][kk][tm+4];
            ull b2[4];
            const ull* bsrc = (const ull*)&Bs[buf][kk][tn];
            b2[0]=bsrc[0]; b2[1]=bsrc[1]; b2[2]=bsrc[2]; b2[3]=bsrc[3];
#pragma unroll
            for (int i = 0; i < 8; i++) {
                ull a2 = pack2(af[i]);
#pragma unroll
                for (int jp = 0; jp < 4; jp++) acc[i][jp] = ffma2(a2, b2[jp], acc[i][jp]);
            }
        }
        if (more) {
            buf ^= 1;
            As[buf][acol+0][arow]=av2.x; As[buf][acol+1][arow]=av2.y;
            As[buf][acol+2][arow]=av2.z; As[buf][acol+3][arow]=av2.w;
            *(float4*)&Bs[buf][brow][bcol] = bv2;
        }
        __syncthreads();
    }
#pragma unroll
    for (int i = 0; i < 8; i++) {
        int gm = bm + tm + i;
        if (gm >= M) continue;
        float* crow = C + (size_t)gm * N + bn + tn;
#pragma unroll
        for (int jp = 0; jp < 4; jp += 2) {
            union { ull u; float2 f; } c0, c1;
            c0.u = acc[i][jp]; c1.u = acc[i][jp+1];
            int j = jp * 2;
            float4 v;
            v.x = c0.f.x + (bias ? bias[bn+tn+j+0] : 0.f);
            v.y = c0.f.y + (bias ? bias[bn+tn+j+1] : 0.f);
            v.z = c1.f.x + (bias ? bias[bn+tn+j+2] : 0.f);
            v.w = c1.f.y + (bias ? bias[bn+tn+j+3] : 0.f);
            if (RELU) {
                v.x=fmaxf(v.x,0.f); v.y=fmaxf(v.y,0.f);
                v.z=fmaxf(v.z,0.f); v.w=fmaxf(v.w,0.f);
            }
            *(float4*)(crow + j) = v;
        }
    }
}

// ---------------- TF32 3-pass MMA GEMM, cp.async double-buffered --------------
// C = A @ B + bias. A hi/lo [M,K=1024] row-major, B hi/lo [1024,N] k-major.
// Stage (floats): Ahi 128x20=2560 | Alo 2560 | Bhi 16x136=2176 | Blo 2176 = 9472
#define STG_F   9472
#define OFF_AL  2560
#define OFF_BH  5120
#define OFF_BL  7296
#define MMA_SM_BYTES ((2 * STG_F + 128) * 4)

__global__ __launch_bounds__(256, 2)
void mma3_gemm(const float* __restrict__ Ahi, const float* __restrict__ Alo,
               const float* __restrict__ Bhi, const float* __restrict__ Blo,
               const float* __restrict__ bias, float* __restrict__ C,
               int ldB, int ldC) {
    extern __shared__ float sm[];
    const u32 sb = smem_u32(sm);
    float* sbias = sm + 2 * STG_F;

    const int tid = threadIdx.x;
    const int w = tid >> 5, lane = tid & 31;
    const int gr = lane >> 2, tq = lane & 3;
    const int warp_m = (w & 3) * 32, warp_n = (w >> 2) * 64;
    const size_t m_base = (size_t)blockIdx.y * 128;
    const int n_base = blockIdx.x * 128;

    if (tid < 128) sbias[tid] = bias[n_base + tid];

    const float* Ah = Ahi + m_base * DECD;
    const float* Al = Alo + m_base * DECD;

    const int lm0 = tid >> 2, lkg = (tid & 3) << 2;   // A loads
    const int lkr = tid >> 5, ln4 = (tid & 31) << 2;  // B loads

    auto load_stage = [&](int s) {
        const int k0 = s << 4;
        const u32 base = sb + ((s & 1) ? STG_F * 4 : 0);
#pragma unroll
        for (int it = 0; it < 2; it++) {
            int m = lm0 + it * 64;
            cp16(base + (u32)(m * 20 + lkg) * 4,           Ah + (size_t)m * DECD + k0 + lkg);
            cp16(base + (u32)(OFF_AL + m * 20 + lkg) * 4,  Al + (size_t)m * DECD + k0 + lkg);
            int kr = lkr + it * 8;
            cp16(base + (u32)(OFF_BH + kr * 136 + ln4) * 4, Bhi + (size_t)(k0 + kr) * ldB + n_base + ln4);
            cp16(base + (u32)(OFF_BL + kr * 136 + ln4) * 4, Blo + (size_t)(k0 + kr) * ldB + n_base + ln4);
        }
        CP_COMMIT();
    };

    float d[2][8][4];
#pragma unroll
    for (int i = 0; i < 2; i++)
#pragma unroll
        for (int j = 0; j < 8; j++)
#pragma unroll
            for (int q = 0; q < 4; q++) d[i][j][q] = 0.0f;

    const int NS = DECD >> 4;  // 64 stages of 16
    load_stage(0);

    for (int s = 0; s < NS; s++) {
        const int buf = s & 1;
        if (s + 1 < NS) { load_stage(s + 1); CP_WAIT1(); }
        else            { CP_WAIT0(); }
        __syncthreads();

        const float* Ash = sm + buf * STG_F;
        const float* Asl = Ash + OFF_AL;
        const float* Bsh = Ash + OFF_BH;
        const float* Bsl = Ash + OFF_BL;

#pragma unroll
        for (int kk = 0; kk < 16; kk += 8) {
            u32 ah[2][4], al[2][4];
#pragma unroll
            for (int i = 0; i < 2; i++) {
                int r = (warp_m + i * 16 + gr) * 20 + kk + tq;
                ah[i][0] = __float_as_uint(Ash[r]);
                ah[i][1] = __float_as_uint(Ash[r + 160]);
                ah[i][2] = __float_as_uint(Ash[r + 4]);
                ah[i][3] = __float_as_uint(Ash[r + 164]);
                al[i][0] = __float_as_uint(Asl[r]);
                al[i][1] = __float_as_uint(Asl[r + 160]);
                al[i][2] = __float_as_uint(Asl[r + 4]);
                al[i][3] = __float_as_uint(Asl[r + 164]);
            }
#pragma unroll
            for (int j = 0; j < 8; j++) {
                int bb = (kk + tq) * 136 + warp_n + j * 8 + gr;
                u32 bh0 = __float_as_uint(Bsh[bb]);
                u32 bh1 = __float_as_uint(Bsh[bb + 544]);
                u32 bl0 = __float_as_uint(Bsl[bb]);
                u32 bl1 = __float_as_uint(Bsl[bb + 544]);
#pragma unroll
                for (int i = 0; i < 2; i++) {
                    mma_tf32(d[i][j], ah[i], bh0, bh1);
                    mma_tf32(d[i][j], ah[i], bl0, bl1);
                    mma_tf32(d[i][j], al[i], bh0, bh1);
                }
            }
        }
        __syncthreads();
    }

    // epilogue
#pragma unroll
    for (int i = 0; i < 2; i++) {
        size_t r0 = m_base + warp_m + i * 16 + gr;
#pragma unroll
        for (int j = 0; j < 8; j++) {
            int cn = warp_n + j * 8 + 2 * tq;
            float bx = sbias[cn], by = sbias[cn + 1];
            float2 v0 = make_float2(d[i][j][0] + bx, d[i][j][1] + by);
            float2 v1 = make_float2(d[i][j][2] + bx, d[i][j][3] + by);
            *(float2*)&C[r0 * ldC + n_base + cn] = v0;
            *(float2*)&C[(r0 + 8) * ldC + n_base + cn] = v1;
        }
    }
}

// ---------------- GRU gate (also emits tf32 split of new h) ------------------
__global__ void gru_gate_kernel(const int* __restrict__ tgt, int t) {
    int idx = blockIdx.x * blockDim.x + threadIdx.x;
    int b = idx >> 10, j = idx & 1023;
    if (b >= B_) return;
    int tok = (t == 0) ? SOS_T : tgt[b * TLEN + (t - 1)];
    size_t base = (size_t)b * G3;
    const float* Erow = g_E + (size_t)tok * G3;

    float ir  = Erow[j]          + g_G0[base + j]          + g_gh[base + j];
    float iz  = Erow[j + DECD]   + g_G0[base + j + DECD]   + g_gh[base + j + DECD];
    float inn = Erow[j + 2*DECD] + g_G0[base + j + 2*DECD];
    float hn  = g_gh[base + j + 2*DECD];

    float r = 1.0f / (1.0f + expf(-ir));
    float z = 1.0f / (1.0f + expf(-iz));
    float n = tanhf(inn + r * hn);
    float hv = g_h[idx];
    float hnew = (1.0f - z) * n + z * hv;
    g_h[idx] = hnew;
    float hi = tf32_rna(hnew);
    g_h_hi[idx] = hi;
    g_h_lo[idx] = tf32_rna(hnew - hi);
}

// ---------------- per-row loss + argmax + scatter -----------------------------
__global__ void loss_argmax_kernel(const int* __restrict__ tgt, int t,
                                   float* __restrict__ pred) {
    int gw = (blockIdx.x * blockDim.x + threadIdx.x) >> 5;
    int lane = threadIdx.x & 31;
    if (gw >= B_) return;
    const float* lg = g_logits + (size_t)gw * VPAD;

    float v[6];
    float vmax = -INFINITY;
    int amax = VOCAB;
#pragma unroll
    for (int i = 0; i < 6; i++) {
        int j = lane + 32 * i;
        v[i] = (j < VOCAB) ? lg[j] : -INFINITY;
        if (v[i] > vmax) { vmax = v[i]; amax = j; }
    }
#pragma unroll
    for (int off = 16; off; off >>= 1) {
        float ov = __shfl_down_sync(0xffffffffu, vmax, off);
        int oi   = __shfl_down_sync(0xffffffffu, amax, off);
        if (ov > vmax || (ov == vmax && oi < amax)) { vmax = ov; amax = oi; }
    }
    vmax = __shfl_sync(0xffffffffu, vmax, 0);
    amax = __shfl_sync(0xffffffffu, amax, 0);

    float se = 0.0f;
#pragma unroll
    for (int i = 0; i < 6; i++) {
        int j = lane + 32 * i;
        if (j < VOCAB) se += expf(v[i] - vmax);
    }
#pragma unroll
    for (int off = 16; off; off >>= 1)
        se += __shfl_down_sync(0xffffffffu, se, off);

    if (lane == 0) {
        int tg = tgt[gw * TLEN + t];
        if (tg != IGN_T) {
            float x = lg[tg];
            g_nll[gw] += -(x - vmax - logf(se));
            g_cnt[gw] += 1;
        }
        if (amax < APRED) pred[(size_t)gw * APRED + amax] = 1.0f;
    }
}

__global__ void finalize_kernel(float* out) {
    __shared__ float sf[1024];
    __shared__ int   si[1024];
    int tid = threadIdx.x;
    float s = 0.f; int c = 0;
    for (int i = tid; i < B_; i += 1024) { s += g_nll[i]; c += g_cnt[i]; }
    sf[tid] = s; si[tid] = c;
    __syncthreads();
    for (int off = 512; off > 0; off >>= 1) {
        if (tid < off) { sf[tid] += sf[tid + off]; si[tid] += si[tid + off]; }
        __syncthreads();
    }
    if (tid == 0) out[0] = sf[0] / fmaxf((float)si[0], 1.0f);
}

// ---------------- launch -------------------------------------------------------
extern "C" void kernel_launch(void* const* d_in, const int* in_sizes, int n_in,
                              void* d_out, int out_size) {
    const float* s   = (const float*)d_in[0];
    const int*   tgt = (const int*)  d_in[1];
    const float* W1  = (const float*)d_in[2];
    const float* b1  = (const float*)d_in[3];
    const float* W2  = (const float*)d_in[4];
    const float* b2  = (const float*)d_in[5];
    const float* emb = (const float*)d_in[6];
    const float* Wih = (const float*)d_in[7];
    const float* Whh = (const float*)d_in[8];
    const float* bih = (const float*)d_in[9];
    const float* bhh = (const float*)d_in[10];
    const float* Wp  = (const float*)d_in[11];
    const float* bp  = (const float*)d_in[12];
    float* out = (float*)d_out;

    float *p_act, *p_h, *p_hhi, *p_hlo, *p_G0, *p_E, *p_gh;
    float *p_Whi, *p_Wlo, *p_Wihi, *p_Wilo, *p_WpPad, *p_Wphi, *p_Wplo, *p_bpPad, *p_logits;
    cudaGetSymbolAddress((void**)&p_act,    g_act);
    cudaGetSymbolAddress((void**)&p_h,      g_h);
    cudaGetSymbolAddress((void**)&p_hhi,    g_h_hi);
    cudaGetSymbolAddress((void**)&p_hlo,    g_h_lo);
    cudaGetSymbolAddress((void**)&p_G0,     g_G0);
    cudaGetSymbolAddress((void**)&p_E,      g_E);
    cudaGetSymbolAddress((void**)&p_gh,     g_gh);
    cudaGetSymbolAddress((void**)&p_Whi,    g_Whi);
    cudaGetSymbolAddress((void**)&p_Wlo,    g_Wlo);
    cudaGetSymbolAddress((void**)&p_Wihi,   g_Wihi);
    cudaGetSymbolAddress((void**)&p_Wilo,   g_Wilo);
    cudaGetSymbolAddress((void**)&p_WpPad,  g_WpPad);
    cudaGetSymbolAddress((void**)&p_Wphi,   g_Wphi);
    cudaGetSymbolAddress((void**)&p_Wplo,   g_Wplo);
    cudaGetSymbolAddress((void**)&p_bpPad,  g_bpPad);
    cudaGetSymbolAddress((void**)&p_logits, g_logits);

    cudaFuncSetAttribute(mma3_gemm, cudaFuncAttributeMaxDynamicSharedMemorySize, MMA_SM_BYTES);

    // init + one-time weight prep
    zero_out_kernel<<<(out_size + 1023) / 1024, 1024>>>(out, out_size);
    zero_acc_kernel<<<(B_ + 1023) / 1024, 1024>>>();
    pad_wp_kernel<<<(DECD * VPAD + 255) / 256, 256>>>(Wp, bp);
    split_kernel<<<(DECD * G3 + 255) / 256, 256>>>(Whh, p_Whi, p_Wlo, DECD * G3);
    split_kernel<<<(DECD * G3 + 255) / 256, 256>>>(Wih + (size_t)EMBD * G3, p_Wihi, p_Wilo, DECD * G3);
    split_kernel<<<(DECD * VPAD + 255) / 256, 256>>>(p_WpPad, p_Wphi, p_Wplo, DECD * VPAD);

    dim3 blk(256);
    // act = relu(s @ W1 + b1)    — exact fp32
    sgemm128<1><<<dim3(HDIM / 128, B_ / 128), blk>>>(s, W1, b1, p_act, B_, HDIM, SDIM);
    // h0 = act @ W2 + b2         — exact fp32
    sgemm128<0><<<dim3(DECD / 128, B_ / 128), blk>>>(p_act, W2, b2, p_h, B_, DECD, HDIM);
    split_kernel<<<(B_ * DECD + 255) / 256, 256>>>(p_h, p_hhi, p_hlo, B_ * DECD);
    // G0 = h0 @ Wih[EMB:,:] + bih  — TF32 3-pass pipelined
    mma3_gemm<<<dim3(G3 / 128, B_ / 128), blk, MMA_SM_BYTES>>>(
        p_hhi, p_hlo, p_Wihi, p_Wilo, bih, p_G0, G3, G3);
    // E = emb @ Wih[:EMB,:]  — exact fp32
    sgemm128<0><<<dim3(G3 / 128, 2), blk>>>(emb, Wih, (const float*)nullptr, p_E, VOCAB, G3, EMBD);

    for (int t = 0; t < TLEN; t++) {
        mma3_gemm<<<dim3(G3 / 128, B_ / 128), blk, MMA_SM_BYTES>>>(
            p_hhi, p_hlo, p_Whi, p_Wlo, bhh, p_gh, G3, G3);
        gru_gate_kernel<<<(B_ * DECD) / 256, 256>>>(tgt, t);
        mma3_gemm<<<dim3(VPAD / 128, B_ / 128), blk, MMA_SM_BYTES>>>(
            p_hhi, p_hlo, p_Wphi, p_Wplo, p_bpPad, p_logits, VPAD, VPAD);
        loss_argmax_kernel<<<B_ / 8, 256>>>(tgt, t, out + 1);
    }

    finalize_kernel<<<1, 1024>>>(out);
}